// round 9
// baseline (speedup 1.0000x reference)
#include <cuda_runtime.h>
#include <math.h>
#include <stdint.h>

// Problem dims
#define NB   128
#define NT   128
#define NC   256
#define NH   4
#define NHS  64
#define NL   6
#define NDFF 1024
#define NV   10000
#define NBT  (NB*NT)
#define NQKV (3*NC)   // 768

// tcgen05 availability: only on arch-specific (sm_103a) or family (sm_103f) passes.
#if defined(__CUDA_ARCH__) && (defined(__CUDA_ARCH_FEAT_SM103_ALL) || \
    (defined(__CUDA_ARCH_SPECIFIC__) && (__CUDA_ARCH_SPECIFIC__ == 1030)) || \
    (defined(__CUDA_ARCH_FAMILY_SPECIFIC__) && (__CUDA_ARCH_FAMILY_SPECIFIC__ == 1030)))
#define HAS_TCGEN05 1
#else
#define HAS_TCGEN05 0
#endif

// ---------------------------------------------------------------------------
// Scratch (device globals)
// ---------------------------------------------------------------------------
__device__ float g_x  [NBT*NC];     // residual stream
__device__ float g_h  [NBT*NC];     // LN output (tf32-rounded)
__device__ float g_qkv[NBT*NQKV];   // fused qkv
__device__ float g_att[NBT*NC];     // attention out (tf32-rounded)
__device__ float g_ff [NBT*NDFF];   // MLP hidden (tf32-rounded)
// tf32-pre-rounded, TRANSPOSED weights: [N][K] K-major
__device__ float g_wqkv [NL*NQKV*NC];
__device__ float g_projw[NL*NC*NC];
__device__ float g_w1   [NL*NDFF*NC];
__device__ float g_w2   [NL*NC*NDFF];
__device__ float g_lmw  [NV*NC];

__device__ __forceinline__ uint32_t f2tf32(float x) {
    uint32_t r;
    asm("cvt.rna.tf32.f32 %0, %1;" : "=r"(r) : "f"(x));
    return r;
}
__device__ __forceinline__ float tf32r(float x) { return __uint_as_float(f2tf32(x)); }

__device__ __forceinline__ uint32_t smem_u32(const void* p) {
    uint32_t a;
    asm("{ .reg .u64 t; cvta.to.shared.u64 t, %1; cvt.u32.u64 %0, t; }" : "=r"(a) : "l"(p));
    return a;
}
__device__ __forceinline__ uint32_t elect_one() {
    uint32_t pred;
    asm volatile("{\n .reg .pred p;\n elect.sync _|p, 0xFFFFFFFF;\n selp.b32 %0, 1, 0, p;\n}" : "=r"(pred));
    return pred;
}
__device__ __forceinline__ void cp16(void* dst, const float* src, bool ok) {
    uint32_t s = smem_u32(dst);
    int sz = ok ? 16 : 0;
    asm volatile("cp.async.cg.shared.global [%0], [%1], 16, %2;\n"
                 :: "r"(s), "l"(src), "r"(sz));
}

// ---------------------------------------------------------------------------
// Weight transpose + tf32 round: src layer l is [K][N] row-major,
// dst is [N][K] row-major (K-major B operand for both GEMM paths).
// ---------------------------------------------------------------------------
__global__ void transpose_round_kernel(const float* __restrict__ src, float* __restrict__ dst,
                                       int K, int N, long srcStride, long dstStride, int dstRowOff) {
    __shared__ float tile[32][33];
    int l = blockIdx.z;
    const float* s = src + (size_t)l * srcStride;
    float* d = dst + (size_t)l * dstStride + (size_t)dstRowOff * K;
    int n0 = blockIdx.x * 32, k0 = blockIdx.y * 32;
    int tx = threadIdx.x, ty = threadIdx.y;   // (32, 8)
    #pragma unroll
    for (int i = 0; i < 32; i += 8) {
        int k = k0 + ty + i, n = n0 + tx;
        tile[ty + i][tx] = (n < N) ? s[(size_t)k * N + n] : 0.f;
    }
    __syncthreads();
    #pragma unroll
    for (int i = 0; i < 32; i += 8) {
        int n = n0 + ty + i, k = k0 + tx;
        if (n < N) d[(size_t)n * K + k] = tf32r(tile[tx][ty + i]);
    }
}

// ---------------------------------------------------------------------------
// Embedding
// ---------------------------------------------------------------------------
__global__ void embed_kernel(const int* __restrict__ idx,
                             const float* __restrict__ tok,
                             const float* __restrict__ pos) {
    int i = blockIdx.x;
    int c = threadIdx.x;
    int t = i & (NT - 1);
    g_x[i*NC + c] = tok[idx[i]*NC + c] + pos[t*NC + c];
}

// ---------------------------------------------------------------------------
// LayerNorm: warp-per-row; output tf32-rounded (feeds MMA GEMMs)
// ---------------------------------------------------------------------------
__global__ void ln_kernel(const float* __restrict__ in, float* __restrict__ out,
                          const float* __restrict__ g, const float* __restrict__ b) {
    int warp = (blockIdx.x * blockDim.x + threadIdx.x) >> 5;
    int lane = threadIdx.x & 31;
    if (warp >= NBT) return;
    const float4* row = (const float4*)(in + (size_t)warp * NC);
    float4 v0 = row[lane];
    float4 v1 = row[lane + 32];
    float s = v0.x+v0.y+v0.z+v0.w + v1.x+v1.y+v1.z+v1.w;
    #pragma unroll
    for (int o = 16; o; o >>= 1) s += __shfl_xor_sync(0xffffffffu, s, o);
    float mean = s * (1.0f / NC);
    float d0x=v0.x-mean, d0y=v0.y-mean, d0z=v0.z-mean, d0w=v0.w-mean;
    float d1x=v1.x-mean, d1y=v1.y-mean, d1z=v1.z-mean, d1w=v1.w-mean;
    float q = d0x*d0x+d0y*d0y+d0z*d0z+d0w*d0w + d1x*d1x+d1y*d1y+d1z*d1z+d1w*d1w;
    #pragma unroll
    for (int o = 16; o; o >>= 1) q += __shfl_xor_sync(0xffffffffu, q, o);
    float rstd = rsqrtf(q * (1.0f / NC) + 1e-5f);
    float4 gg0 = ((const float4*)g)[lane];
    float4 gg1 = ((const float4*)g)[lane + 32];
    float4 bb0 = ((const float4*)b)[lane];
    float4 bb1 = ((const float4*)b)[lane + 32];
    float4 o0, o1;
    o0.x = tf32r(d0x*rstd*gg0.x + bb0.x);  o0.y = tf32r(d0y*rstd*gg0.y + bb0.y);
    o0.z = tf32r(d0z*rstd*gg0.z + bb0.z);  o0.w = tf32r(d0w*rstd*gg0.w + bb0.w);
    o1.x = tf32r(d1x*rstd*gg1.x + bb1.x);  o1.y = tf32r(d1y*rstd*gg1.y + bb1.y);
    o1.z = tf32r(d1z*rstd*gg1.z + bb1.z);  o1.w = tf32r(d1w*rstd*gg1.w + bb1.w);
    float4* orow = (float4*)(out + (size_t)warp * NC);
    orow[lane]      = o0;
    orow[lane + 32] = o1;
}

// ---------------------------------------------------------------------------
// Shared GEMM entry: out[M,N] = A[M,K] @ Wt[N,K]^T (+bias)(+res)(relu)(round)
// sm_103a pass: tcgen05 SS pipeline (128x128 tile, K-chunk 64, double buffer).
// sm_103 pass:  mma.sync tf32 (128x128 tile, BK=32, double buffer).
// ---------------------------------------------------------------------------
#define TCG_SMEM (1024 + 4*32768)   // 132096 bytes

#if !HAS_TCGEN05
__device__ __forceinline__ void mma_tf32(float* d, const uint32_t* a, const uint32_t* b) {
    asm volatile(
        "mma.sync.aligned.m16n8k8.row.col.f32.tf32.tf32.f32 "
        "{%0,%1,%2,%3}, {%4,%5,%6,%7}, {%8,%9}, {%0,%1,%2,%3};\n"
        : "+f"(d[0]), "+f"(d[1]), "+f"(d[2]), "+f"(d[3])
        : "r"(a[0]), "r"(a[1]), "r"(a[2]), "r"(a[3]), "r"(b[0]), "r"(b[1]));
}
#endif

#if HAS_TCGEN05
// SW128 K-major descriptor base: layout=2(SW128), version=1, SBO=64, LBO=1
#define DESC_BASE ((uint64_t(2) << 61) | (uint64_t(1) << 46) | (uint64_t(64) << 32) | (uint64_t(1) << 16))
#define MK_DESC(addr) (DESC_BASE | ((uint64_t)((addr) >> 4) & 0x3FFF))
// idesc: dtype=F32(1)@4, atype=TF32(2)@7, btype=TF32(2)@10, N/8=16@17, M/16=8@24
#define TC_IDESC ((1u << 4) | (2u << 7) | (2u << 10) | (16u << 17) | (8u << 24))

__device__ __forceinline__ void tc_mma_tf32_ss(uint32_t d_tmem, uint64_t a_desc,
                                               uint64_t b_desc, uint32_t idesc,
                                               uint32_t enable) {
    asm volatile(
        "{\n\t"
        ".reg .pred p;\n\t"
        "setp.ne.u32 p, %4, 0;\n\t"
        "tcgen05.mma.cta_group::1.kind::tf32 [%0], %1, %2, %3, {%5, %5, %5, %5}, p;\n\t"
        "}"
        :: "r"(d_tmem), "l"(a_desc), "l"(b_desc), "r"(idesc), "r"(enable), "r"(0u)
        : "memory");
}

__device__ __forceinline__ void mbar_wait(uint32_t mbar, uint32_t parity) {
    uint32_t done;
    asm volatile(
        "{\n .reg .pred p;\n"
        " mbarrier.try_wait.parity.acquire.cta.shared::cta.b64 p, [%1], %2;\n"
        " selp.b32 %0, 1, 0, p;\n}"
        : "=r"(done) : "r"(mbar), "r"(parity) : "memory");
    if (!done) {
        asm volatile(
            "{\n .reg .pred P1;\n"
            "WL_%=:\n"
            " mbarrier.try_wait.parity.acquire.cta.shared::cta.b64 P1, [%0], %1, 0x989680;\n"
            " @P1 bra.uni WD_%=;\n"
            " bra.uni WL_%=;\n"
            "WD_%=:\n}"
            :: "r"(mbar), "r"(parity) : "memory");
    }
}
#endif

template<bool BIAS, bool RES, bool RELU, bool ROUND>
__global__ void __launch_bounds__(256, 1)
tc_gemm(const float* __restrict__ A, const float* __restrict__ Wt,
        const float* __restrict__ bias, const float* __restrict__ res,
        float* __restrict__ out, int M, int N, int K) {
    int tid  = threadIdx.x;
    int wid  = tid >> 5;
    int lane = tid & 31;
    int row0 = blockIdx.y * 128;
    int col0 = blockIdx.x * 128;

#if HAS_TCGEN05
    // ======================= tcgen05 path (sm_103a) =======================
    extern __shared__ char smem[];
    uint32_t sb = smem_u32(smem);

    if (wid == 0) {
        asm volatile("tcgen05.alloc.cta_group::1.sync.aligned.shared::cta.b32 [%0], %1;"
                     :: "r"(sb), "r"(128u) : "memory");
    }
    if (tid == 0) {
        asm volatile("mbarrier.init.shared.b64 [%0], 1;" :: "r"(sb + 8)  : "memory");
        asm volatile("mbarrier.init.shared.b64 [%0], 1;" :: "r"(sb + 16) : "memory");
    }
    __syncthreads();
    uint32_t tmem;
    asm volatile("ld.shared.b32 %0, [%1];" : "=r"(tmem) : "r"(sb));

    // stage: 128 rows x 64 tf32 (256B/row) in blocked SW128 atoms
    // atom = 8 rows x 128B; 16 atom-rows, 2 atom-cols; atom_off = arow + acol*16
    auto fill = [&](int s, int k0) {
        char* bufA = smem + 1024 + s * 32768;
        char* bufB = smem + 1024 + 65536 + s * 32768;
        #pragma unroll
        for (int i = 0; i < 8; i++) {
            int e = tid + i * 256;
            int row = e >> 4, kc = e & 15;
            uint32_t byte = (((row >> 3) + ((kc >> 3) << 4)) << 10) + ((row & 7) << 7) + ((kc & 7) << 4);
            uint32_t sw = byte ^ ((byte >> 3) & 0x70);
            cp16(bufA + sw, &A[(size_t)(row0 + row) * K + k0 + kc * 4], true);
        }
        #pragma unroll
        for (int i = 0; i < 8; i++) {
            int e = tid + i * 256;
            int row = e >> 4, kc = e & 15;
            uint32_t byte = (((row >> 3) + ((kc >> 3) << 4)) << 10) + ((row & 7) << 7) + ((kc & 7) << 4);
            uint32_t sw = byte ^ ((byte >> 3) & 0x70);
            bool ok = (col0 + row) < N;
            int srow = ok ? (col0 + row) : 0;
            cp16(bufB + sw, &Wt[(size_t)srow * K + k0 + kc * 4], ok);
        }
        asm volatile("cp.async.commit_group;\n");
    };

    int nst = K >> 6;
    fill(0, 0);
    for (int i = 0; i < nst; i++) {
        int buf = i & 1;
        if (i + 1 < nst) {
            if (i >= 1)   // stage i+1 reuses buffer of stage i-1; wait its MMA commit
                mbar_wait(sb + 8 + ((i - 1) & 1) * 8, ((i - 1) >> 1) & 1);
            fill(buf ^ 1, (i + 1) << 6);
            asm volatile("cp.async.wait_group 1;\n" ::: "memory");
        } else {
            asm volatile("cp.async.wait_group 0;\n" ::: "memory");
        }
        asm volatile("fence.proxy.async.shared::cta;" ::: "memory");
        __syncthreads();

        if (wid == 0 && elect_one()) {
            uint64_t ad = MK_DESC(sb + 1024 + buf * 32768);
            uint64_t bd = MK_DESC(sb + 1024 + 65536 + buf * 32768);
            #pragma unroll
            for (int s = 0; s < 8; s++) {
                // k-step s: atom_col (s>>2) at +16KB = 1024 16B-units; within col +32B = 2 units
                uint32_t off = ((s >> 2) << 10) + ((s & 3) << 1);
                tc_mma_tf32_ss(tmem, ad + off, bd + off, TC_IDESC, (i | s) != 0);
            }
            asm volatile(
                "tcgen05.commit.cta_group::1.mbarrier::arrive::one.shared::cluster.b64 [%0];"
                :: "r"(sb + 8 + buf * 8) : "memory");
        }
    }

    mbar_wait(sb + 8 + ((nst - 1) & 1) * 8, ((nst - 1) >> 1) & 1);
    asm volatile("tcgen05.fence::after_thread_sync;" ::: "memory");

    if (wid < 4) {
        int r = row0 + wid * 32 + lane;
        #pragma unroll
        for (int cb = 0; cb < 4; cb++) {
            uint32_t rg[32];
            asm volatile(
                "tcgen05.ld.sync.aligned.32x32b.x32.b32 "
                "{%0,%1,%2,%3,%4,%5,%6,%7,%8,%9,%10,%11,%12,%13,%14,%15,"
                "%16,%17,%18,%19,%20,%21,%22,%23,%24,%25,%26,%27,%28,%29,%30,%31}, [%32];"
                : "=r"(rg[0]), "=r"(rg[1]), "=r"(rg[2]), "=r"(rg[3]),
                  "=r"(rg[4]), "=r"(rg[5]), "=r"(rg[6]), "=r"(rg[7]),
                  "=r"(rg[8]), "=r"(rg[9]), "=r"(rg[10]), "=r"(rg[11]),
                  "=r"(rg[12]), "=r"(rg[13]), "=r"(rg[14]), "=r"(rg[15]),
                  "=r"(rg[16]), "=r"(rg[17]), "=r"(rg[18]), "=r"(rg[19]),
                  "=r"(rg[20]), "=r"(rg[21]), "=r"(rg[22]), "=r"(rg[23]),
                  "=r"(rg[24]), "=r"(rg[25]), "=r"(rg[26]), "=r"(rg[27]),
                  "=r"(rg[28]), "=r"(rg[29]), "=r"(rg[30]), "=r"(rg[31])
                : "r"(tmem + cb * 32));
            asm volatile("tcgen05.wait::ld.sync.aligned;" ::: "memory");
            #pragma unroll
            for (int gq = 0; gq < 8; gq++) {
                int c = col0 + cb * 32 + gq * 4;
                if (c < N) {
                    float v0 = __uint_as_float(rg[gq*4+0]);
                    float v1 = __uint_as_float(rg[gq*4+1]);
                    float v2 = __uint_as_float(rg[gq*4+2]);
                    float v3 = __uint_as_float(rg[gq*4+3]);
                    if (BIAS) {
                        float4 bv = *(const float4*)&bias[c];
                        v0 += bv.x; v1 += bv.y; v2 += bv.z; v3 += bv.w;
                    }
                    if (RES) {
                        float4 rv = *(const float4*)&res[(size_t)r * N + c];
                        v0 += rv.x; v1 += rv.y; v2 += rv.z; v3 += rv.w;
                    }
                    if (RELU) {
                        v0 = fmaxf(v0, 0.f); v1 = fmaxf(v1, 0.f);
                        v2 = fmaxf(v2, 0.f); v3 = fmaxf(v3, 0.f);
                    }
                    if (ROUND) {
                        v0 = tf32r(v0); v1 = tf32r(v1); v2 = tf32r(v2); v3 = tf32r(v3);
                    }
                    *(float4*)&out[(size_t)r * N + c] = make_float4(v0, v1, v2, v3);
                }
            }
        }
        asm volatile("tcgen05.fence::before_thread_sync;" ::: "memory");
    }
    __syncthreads();
    if (wid == 0) {
        asm volatile("tcgen05.dealloc.cta_group::1.sync.aligned.b32 %0, %1;"
                     :: "r"(tmem), "r"(128u));
    }
#else
    // ======================= mma.sync fallback (sm_103) =======================
    extern __shared__ float fsm[];
    float (*As)[128][36] = reinterpret_cast<float (*)[128][36]>(fsm);
    float (*Bs)[128][36] = reinterpret_cast<float (*)[128][36]>(fsm + 2*128*36);

    int wm = (wid & 1) * 64;
    int wn = (wid >> 1) * 32;

    float acc[16][4];
    #pragma unroll
    for (int i = 0; i < 16; i++)
        #pragma unroll
        for (int j = 0; j < 4; j++) acc[i][j] = 0.f;

    auto load_stage = [&](int s, int k0) {
        #pragma unroll
        for (int i = 0; i < 4; i++) {
            int lin = tid + i * 256;
            int r = lin >> 3, kq = (lin & 7) * 4;
            cp16(&As[s][r][kq], &A[(size_t)(row0 + r) * K + k0 + kq], true);
        }
        #pragma unroll
        for (int i = 0; i < 4; i++) {
            int lin = tid + i * 256;
            int r = lin >> 3, kq = (lin & 7) * 4;
            bool ok = (col0 + r) < N;
            int sr = ok ? (col0 + r) : 0;
            cp16(&Bs[s][r][kq], &Wt[(size_t)sr * K + k0 + kq], ok);
        }
        asm volatile("cp.async.commit_group;\n");
    };

    int nk = K >> 5;
    load_stage(0, 0);
    for (int i = 0; i < nk; i++) {
        int buf = i & 1;
        if (i + 1 < nk) {
            load_stage(buf ^ 1, (i + 1) << 5);
            asm volatile("cp.async.wait_group 1;\n");
        } else {
            asm volatile("cp.async.wait_group 0;\n");
        }
        __syncthreads();

        #pragma unroll
        for (int ks = 0; ks < 32; ks += 8) {
            uint32_t af[4][4], bf[4][2];
            int arow = wm + (lane >> 2);
            int akc  = ks + (lane & 3);
            #pragma unroll
            for (int mt = 0; mt < 4; mt++) {
                af[mt][0] = __float_as_uint(As[buf][arow + mt*16    ][akc    ]);
                af[mt][1] = __float_as_uint(As[buf][arow + mt*16 + 8][akc    ]);
                af[mt][2] = __float_as_uint(As[buf][arow + mt*16    ][akc + 4]);
                af[mt][3] = __float_as_uint(As[buf][arow + mt*16 + 8][akc + 4]);
            }
            #pragma unroll
            for (int nt = 0; nt < 4; nt++) {
                int ncol = wn + nt*8 + (lane >> 2);
                bf[nt][0] = __float_as_uint(Bs[buf][ncol][akc    ]);
                bf[nt][1] = __float_as_uint(Bs[buf][ncol][akc + 4]);
            }
            #pragma unroll
            for (int mt = 0; mt < 4; mt++)
                #pragma unroll
                for (int nt = 0; nt < 4; nt++)
                    mma_tf32(acc[mt*4 + nt], af[mt], bf[nt]);
        }
        __syncthreads();
    }

    #pragma unroll
    for (int mt = 0; mt < 4; mt++) {
        #pragma unroll
        for (int nt = 0; nt < 4; nt++) {
            float* a = acc[mt*4 + nt];
            int r = row0 + wm + mt*16 + (lane >> 2);
            int c = col0 + wn + nt*8 + (lane & 3)*2;
            if (c < N) {
                float b0 = 0.f, b1 = 0.f;
                if (BIAS) { b0 = bias[c]; b1 = bias[c+1]; }
                float v0 = a[0] + b0, v1 = a[1] + b1;
                float v2 = a[2] + b0, v3 = a[3] + b1;
                if (RES) {
                    v0 += res[(size_t)r * N + c];     v1 += res[(size_t)r * N + c + 1];
                    v2 += res[(size_t)(r+8) * N + c]; v3 += res[(size_t)(r+8) * N + c + 1];
                }
                if (RELU) {
                    v0 = fmaxf(v0, 0.f); v1 = fmaxf(v1, 0.f);
                    v2 = fmaxf(v2, 0.f); v3 = fmaxf(v3, 0.f);
                }
                if (ROUND) {
                    v0 = tf32r(v0); v1 = tf32r(v1); v2 = tf32r(v2); v3 = tf32r(v3);
                }
                *(float2*)&out[(size_t)r * N + c]     = make_float2(v0, v1);
                *(float2*)&out[(size_t)(r+8) * N + c] = make_float2(v2, v3);
            }
        }
    }
#endif
}

// ---------------------------------------------------------------------------
// Causal attention: reads fused qkv [NBT][768]; writes att [NBT][256] rounded.
// ---------------------------------------------------------------------------
__global__ void attn_kernel(const float* __restrict__ qkv, float* __restrict__ att) {
    extern __shared__ float sm[];
    float* ks = sm;
    float* vs = sm + NT * NHS;
    int bh = blockIdx.x;
    int b = bh / NH, h = bh % NH;
    size_t rbase = (size_t)(b * NT) * NQKV + h * NHS;
    int tid = threadIdx.x;

    for (int e = tid; e < NT * NHS / 4; e += 256) {
        int t  = e >> 4;
        int dq = e & 15;
        ((float4*)ks)[e] = *(const float4*)&qkv[rbase + NC   + (size_t)t * NQKV + dq * 4];
        ((float4*)vs)[e] = *(const float4*)&qkv[rbase + 2*NC + (size_t)t * NQKV + dq * 4];
    }
    __syncthreads();

    int warp = tid >> 5, lane = tid & 31;
    const float scale = 0.0625f;   // C^-0.5 (C=256), per reference
    for (int tq = warp; tq < NT; tq += 8) {
        float2 qv = *(const float2*)&qkv[rbase + (size_t)tq * NQKV + lane * 2];
        float m = -1e30f, l = 0.f, a0 = 0.f, a1 = 0.f;
        for (int j = 0; j <= tq; j++) {
            float d = qv.x * ks[j*NHS + lane*2] + qv.y * ks[j*NHS + lane*2 + 1];
            #pragma unroll
            for (int o = 16; o; o >>= 1) d += __shfl_xor_sync(0xffffffffu, d, o);
            float s  = d * scale;
            float mn = fmaxf(m, s);
            float cf = __expf(m - mn);
            float p  = __expf(s - mn);
            l  = l * cf + p;
            a0 = a0 * cf + p * vs[j*NHS + lane*2];
            a1 = a1 * cf + p * vs[j*NHS + lane*2 + 1];
            m = mn;
        }
        float inv = 1.0f / l;
        size_t obase = (size_t)(b * NT + tq) * NC + h * NHS;
        att[obase + lane*2]     = tf32r(a0 * inv);
        att[obase + lane*2 + 1] = tf32r(a1 * inv);
    }
}

// ---------------------------------------------------------------------------
// Host launcher
// ---------------------------------------------------------------------------
extern "C" void kernel_launch(void* const* d_in, const int* in_sizes, int n_in,
                              void* d_out, int out_size) {
    const int*   idx     = (const int*)  d_in[0];
    const float* tok_emb = (const float*)d_in[1];
    const float* pos_emb = (const float*)d_in[2];
    const float* ln1_g   = (const float*)d_in[3];
    const float* ln1_b   = (const float*)d_in[4];
    const float* wq      = (const float*)d_in[5];
    const float* wk      = (const float*)d_in[6];
    const float* wv      = (const float*)d_in[7];
    const float* proj_w  = (const float*)d_in[8];
    const float* proj_b  = (const float*)d_in[9];
    const float* ln2_g   = (const float*)d_in[10];
    const float* ln2_b   = (const float*)d_in[11];
    const float* w1      = (const float*)d_in[12];
    const float* b1      = (const float*)d_in[13];
    const float* w2      = (const float*)d_in[14];
    const float* b2      = (const float*)d_in[15];
    const float* lnf_g   = (const float*)d_in[16];
    const float* lnf_b   = (const float*)d_in[17];
    const float* lm_w    = (const float*)d_in[18];
    const float* lm_b    = (const float*)d_in[19];
    float* out = (float*)d_out;

    float *x, *h, *qkv, *att, *ff;
    float *wqkvT, *projwT, *pw1T, *pw2T, *lmwT;
    cudaGetSymbolAddress((void**)&x,     g_x);
    cudaGetSymbolAddress((void**)&h,     g_h);
    cudaGetSymbolAddress((void**)&qkv,   g_qkv);
    cudaGetSymbolAddress((void**)&att,   g_att);
    cudaGetSymbolAddress((void**)&ff,    g_ff);
    cudaGetSymbolAddress((void**)&wqkvT, g_wqkv);
    cudaGetSymbolAddress((void**)&projwT,g_projw);
    cudaGetSymbolAddress((void**)&pw1T,  g_w1);
    cudaGetSymbolAddress((void**)&pw2T,  g_w2);
    cudaGetSymbolAddress((void**)&lmwT,  g_lmw);

    cudaFuncSetAttribute(attn_kernel, cudaFuncAttributeMaxDynamicSharedMemorySize,
                         2 * NT * NHS * (int)sizeof(float));
    cudaFuncSetAttribute(tc_gemm<false,false,false,false>,
                         cudaFuncAttributeMaxDynamicSharedMemorySize, TCG_SMEM);
    cudaFuncSetAttribute(tc_gemm<true,true,false,false>,
                         cudaFuncAttributeMaxDynamicSharedMemorySize, TCG_SMEM);
    cudaFuncSetAttribute(tc_gemm<true,false,true,true>,
                         cudaFuncAttributeMaxDynamicSharedMemorySize, TCG_SMEM);
    cudaFuncSetAttribute(tc_gemm<true,false,false,false>,
                         cudaFuncAttributeMaxDynamicSharedMemorySize, TCG_SMEM);

    // ---- weight transpose + tf32 pre-round (scratch, once per replay) ----
    dim3 tb(32, 8);
    transpose_round_kernel<<<dim3(8, 8, NL), tb>>>(wq, wqkvT, NC, NC,
        (long)NC*NC, (long)NQKV*NC, 0);
    transpose_round_kernel<<<dim3(8, 8, NL), tb>>>(wk, wqkvT, NC, NC,
        (long)NC*NC, (long)NQKV*NC, NC);
    transpose_round_kernel<<<dim3(8, 8, NL), tb>>>(wv, wqkvT, NC, NC,
        (long)NC*NC, (long)NQKV*NC, 2*NC);
    transpose_round_kernel<<<dim3(8, 8, NL), tb>>>(proj_w, projwT, NC, NC,
        (long)NC*NC, (long)NC*NC, 0);
    transpose_round_kernel<<<dim3(32, 8, NL), tb>>>(w1, pw1T, NC, NDFF,
        (long)NC*NDFF, (long)NDFF*NC, 0);
    transpose_round_kernel<<<dim3(8, 32, NL), tb>>>(w2, pw2T, NDFF, NC,
        (long)NDFF*NC, (long)NC*NDFF, 0);
    transpose_round_kernel<<<dim3(313, 8, 1), tb>>>(lm_w, lmwT, NC, NV,
        (long)NC*NV, (long)NV*NC, 0);

    embed_kernel<<<NBT, NC>>>(idx, tok_emb, pos_emb);

    for (int l = 0; l < NL; l++) {
        ln_kernel<<<NBT / 8, 256>>>(x, h, ln1_g + l*NC, ln1_b + l*NC);
        tc_gemm<false,false,false,false><<<dim3(NQKV/128, NBT/128), 256, TCG_SMEM>>>(
            h, wqkvT + (size_t)l*NQKV*NC, nullptr, nullptr, qkv, NBT, NQKV, NC);
        attn_kernel<<<NB * NH, 256, 2 * NT * NHS * (int)sizeof(float)>>>(qkv, att);
        tc_gemm<true,true,false,false><<<dim3(NC/128, NBT/128), 256, TCG_SMEM>>>(
            att, projwT + (size_t)l*NC*NC, proj_b + l*NC, x, x, NBT, NC, NC);
        ln_kernel<<<NBT / 8, 256>>>(x, h, ln2_g + l*NC, ln2_b + l*NC);
        tc_gemm<true,false,true,true><<<dim3(NDFF/128, NBT/128), 256, TCG_SMEM>>>(
            h, pw1T + (size_t)l*NDFF*NC, b1 + l*NDFF, nullptr, ff, NBT, NDFF, NC);
        tc_gemm<true,true,false,false><<<dim3(NC/128, NBT/128), 256, TCG_SMEM>>>(
            ff, pw2T + (size_t)l*NC*NDFF, b2 + l*NC, x, x, NBT, NC, NDFF);
    }

    ln_kernel<<<NBT / 8, 256>>>(x, h, lnf_g, lnf_b);
    tc_gemm<true,false,false,false><<<dim3((NV + 127)/128, NBT/128), 256, TCG_SMEM>>>(
        h, lmwT, lm_b, nullptr, out, NBT, NV, NC);
}

// round 10
// speedup vs baseline: 1.5397x; 1.5397x over previous
#include <cuda_runtime.h>
#include <math.h>
#include <stdint.h>

// Problem dims
#define NB   128
#define NT   128
#define NC   256
#define NH   4
#define NHS  64
#define NL   6
#define NDFF 1024
#define NV   10000
#define NBT  (NB*NT)
#define NQKV (3*NC)   // 768

// ---------------------------------------------------------------------------
// Scratch (device globals)
// ---------------------------------------------------------------------------
__device__ float g_x  [NBT*NC];     // residual stream
__device__ float g_h  [NBT*NC];     // LN output (tf32-rounded)
__device__ float g_qkv[NBT*NQKV];   // fused qkv
__device__ float g_att[NBT*NC];     // attention out (tf32-rounded)
__device__ float g_ff [NBT*NDFF];   // MLP hidden (tf32-rounded)
// tf32-pre-rounded weights, [K][N] layout
__device__ float g_wqkv [NL*NC*NQKV];
__device__ float g_projw[NL*NC*NC];
__device__ float g_w1   [NL*NC*NDFF];
__device__ float g_w2   [NL*NDFF*NC];
__device__ float g_lmw  [NC*NV];

__device__ __forceinline__ uint32_t f2tf32(float x) {
    uint32_t r;
    asm("cvt.rna.tf32.f32 %0, %1;" : "=r"(r) : "f"(x));
    return r;
}
__device__ __forceinline__ float tf32r(float x) { return __uint_as_float(f2tf32(x)); }

// ---------------------------------------------------------------------------
// Weight pre-rounding / packing (once per replay)
// ---------------------------------------------------------------------------
__global__ void pack_qkv_kernel(const float* __restrict__ wq,
                                const float* __restrict__ wk,
                                const float* __restrict__ wv) {
    int e = blockIdx.x * 256 + threadIdx.x;        // < NL*NC*NC
    int l = e / (NC*NC);
    int rc = e % (NC*NC);
    int r = rc / NC, c = rc % NC;
    float* dst = g_wqkv + (size_t)(l*NC + r) * NQKV;
    dst[c]          = tf32r(wq[e]);
    dst[NC + c]     = tf32r(wk[e]);
    dst[2*NC + c]   = tf32r(wv[e]);
}
__global__ void round_kernel(const float* __restrict__ in, float* __restrict__ out, int n4) {
    int i = blockIdx.x * 256 + threadIdx.x;
    if (i < n4) {
        float4 v = ((const float4*)in)[i];
        v.x = tf32r(v.x); v.y = tf32r(v.y); v.z = tf32r(v.z); v.w = tf32r(v.w);
        ((float4*)out)[i] = v;
    }
}

// ---------------------------------------------------------------------------
// Embedding
// ---------------------------------------------------------------------------
__global__ void embed_kernel(const int* __restrict__ idx,
                             const float* __restrict__ tok,
                             const float* __restrict__ pos) {
    int i = blockIdx.x;
    int c = threadIdx.x;
    int t = i & (NT - 1);
    g_x[i*NC + c] = tok[idx[i]*NC + c] + pos[t*NC + c];
}

// ---------------------------------------------------------------------------
// LayerNorm: warp-per-row; output tf32-rounded (feeds MMA GEMMs)
// ---------------------------------------------------------------------------
__global__ void ln_kernel(const float* __restrict__ in, float* __restrict__ out,
                          const float* __restrict__ g, const float* __restrict__ b) {
    int warp = (blockIdx.x * blockDim.x + threadIdx.x) >> 5;
    int lane = threadIdx.x & 31;
    if (warp >= NBT) return;
    const float4* row = (const float4*)(in + (size_t)warp * NC);
    float4 v0 = row[lane];
    float4 v1 = row[lane + 32];
    float s = v0.x+v0.y+v0.z+v0.w + v1.x+v1.y+v1.z+v1.w;
    #pragma unroll
    for (int o = 16; o; o >>= 1) s += __shfl_xor_sync(0xffffffffu, s, o);
    float mean = s * (1.0f / NC);
    float d0x=v0.x-mean, d0y=v0.y-mean, d0z=v0.z-mean, d0w=v0.w-mean;
    float d1x=v1.x-mean, d1y=v1.y-mean, d1z=v1.z-mean, d1w=v1.w-mean;
    float q = d0x*d0x+d0y*d0y+d0z*d0z+d0w*d0w + d1x*d1x+d1y*d1y+d1z*d1z+d1w*d1w;
    #pragma unroll
    for (int o = 16; o; o >>= 1) q += __shfl_xor_sync(0xffffffffu, q, o);
    float rstd = rsqrtf(q * (1.0f / NC) + 1e-5f);
    float4 gg0 = ((const float4*)g)[lane];
    float4 gg1 = ((const float4*)g)[lane + 32];
    float4 bb0 = ((const float4*)b)[lane];
    float4 bb1 = ((const float4*)b)[lane + 32];
    float4 o0, o1;
    o0.x = tf32r(d0x*rstd*gg0.x + bb0.x);  o0.y = tf32r(d0y*rstd*gg0.y + bb0.y);
    o0.z = tf32r(d0z*rstd*gg0.z + bb0.z);  o0.w = tf32r(d0w*rstd*gg0.w + bb0.w);
    o1.x = tf32r(d1x*rstd*gg1.x + bb1.x);  o1.y = tf32r(d1y*rstd*gg1.y + bb1.y);
    o1.z = tf32r(d1z*rstd*gg1.z + bb1.z);  o1.w = tf32r(d1w*rstd*gg1.w + bb1.w);
    float4* orow = (float4*)(out + (size_t)warp * NC);
    orow[lane]      = o0;
    orow[lane + 32] = o1;
}

// ---------------------------------------------------------------------------
// TF32 MMA GEMM (R7 config): cp.async double-buffered, block 128x128, BK=32,
// 256 threads, warp tile 64x32 (m16n8k8). Inputs pre-rounded to tf32.
// ---------------------------------------------------------------------------
__device__ __forceinline__ void mma_tf32(float* d, const uint32_t* a, const uint32_t* b) {
    asm volatile(
        "mma.sync.aligned.m16n8k8.row.col.f32.tf32.tf32.f32 "
        "{%0,%1,%2,%3}, {%4,%5,%6,%7}, {%8,%9}, {%0,%1,%2,%3};\n"
        : "+f"(d[0]), "+f"(d[1]), "+f"(d[2]), "+f"(d[3])
        : "r"(a[0]), "r"(a[1]), "r"(a[2]), "r"(a[3]), "r"(b[0]), "r"(b[1]));
}
__device__ __forceinline__ void cp16(float* dst, const float* src, bool ok) {
    uint32_t s = (uint32_t)__cvta_generic_to_shared(dst);
    int sz = ok ? 16 : 0;
    asm volatile("cp.async.cg.shared.global [%0], [%1], 16, %2;\n"
                 :: "r"(s), "l"(src), "r"(sz));
}

#define GEMM_SMEM ((2*128*36 + 2*32*136) * 4)   // 71680 bytes

template<bool BIAS, bool RES, bool RELU, bool ROUND>
__global__ void __launch_bounds__(256, 2)
mma_gemm(const float* __restrict__ A, const float* __restrict__ W,
         const float* __restrict__ bias, const float* __restrict__ res,
         float* __restrict__ out, int M, int N, int K) {
    extern __shared__ float smem[];
    float (*As)[128][36] = reinterpret_cast<float (*)[128][36]>(smem);
    float (*Bs)[32][136] = reinterpret_cast<float (*)[32][136]>(smem + 2*128*36);

    int tid  = threadIdx.x;
    int lane = tid & 31;
    int wid  = tid >> 5;
    int row0 = blockIdx.y * 128;
    int col0 = blockIdx.x * 128;
    int wm = (wid & 1) * 64;
    int wn = (wid >> 1) * 32;

    float acc[16][4];
    #pragma unroll
    for (int i = 0; i < 16; i++)
        #pragma unroll
        for (int j = 0; j < 4; j++) acc[i][j] = 0.f;

    auto load_stage = [&](int s, int k0) {
        #pragma unroll
        for (int i = 0; i < 4; i++) {
            int lin = tid + i * 256;
            int r = lin >> 3, kq = (lin & 7) * 4;
            cp16(&As[s][r][kq], &A[(size_t)(row0 + r) * K + k0 + kq], true);
        }
        #pragma unroll
        for (int i = 0; i < 4; i++) {
            int lin = tid + i * 256;
            int kr = lin >> 5, cc = (lin & 31) * 4;
            cp16(&Bs[s][kr][cc], &W[(size_t)(k0 + kr) * N + col0 + cc], col0 + cc < N);
        }
        asm volatile("cp.async.commit_group;\n");
    };

    int nk = K >> 5;
    load_stage(0, 0);
    for (int i = 0; i < nk; i++) {
        int buf = i & 1;
        if (i + 1 < nk) {
            load_stage(buf ^ 1, (i + 1) << 5);
            asm volatile("cp.async.wait_group 1;\n");
        } else {
            asm volatile("cp.async.wait_group 0;\n");
        }
        __syncthreads();

        #pragma unroll
        for (int ks = 0; ks < 32; ks += 8) {
            uint32_t af[4][4], bf[4][2];
            int arow = wm + (lane >> 2);
            int akc  = ks + (lane & 3);
            #pragma unroll
            for (int mt = 0; mt < 4; mt++) {
                af[mt][0] = __float_as_uint(As[buf][arow + mt*16    ][akc    ]);
                af[mt][1] = __float_as_uint(As[buf][arow + mt*16 + 8][akc    ]);
                af[mt][2] = __float_as_uint(As[buf][arow + mt*16    ][akc + 4]);
                af[mt][3] = __float_as_uint(As[buf][arow + mt*16 + 8][akc + 4]);
            }
            #pragma unroll
            for (int nt = 0; nt < 4; nt++) {
                int ncol = wn + nt*8 + (lane >> 2);
                bf[nt][0] = __float_as_uint(Bs[buf][ks + (lane & 3)    ][ncol]);
                bf[nt][1] = __float_as_uint(Bs[buf][ks + 4 + (lane & 3)][ncol]);
            }
            #pragma unroll
            for (int mt = 0; mt < 4; mt++)
                #pragma unroll
                for (int nt = 0; nt < 4; nt++)
                    mma_tf32(acc[mt*4 + nt], af[mt], bf[nt]);
        }
        __syncthreads();
    }

    #pragma unroll
    for (int mt = 0; mt < 4; mt++) {
        #pragma unroll
        for (int nt = 0; nt < 4; nt++) {
            float* a = acc[mt*4 + nt];
            int r = row0 + wm + mt*16 + (lane >> 2);
            int c = col0 + wn + nt*8 + (lane & 3)*2;
            if (c < N) {
                float b0 = 0.f, b1 = 0.f;
                if (BIAS) { b0 = bias[c]; b1 = bias[c+1]; }
                float v0 = a[0] + b0, v1 = a[1] + b1;
                float v2 = a[2] + b0, v3 = a[3] + b1;
                if (RES) {
                    v0 += res[(size_t)r * N + c];     v1 += res[(size_t)r * N + c + 1];
                    v2 += res[(size_t)(r+8) * N + c]; v3 += res[(size_t)(r+8) * N + c + 1];
                }
                if (RELU) {
                    v0 = fmaxf(v0, 0.f); v1 = fmaxf(v1, 0.f);
                    v2 = fmaxf(v2, 0.f); v3 = fmaxf(v3, 0.f);
                }
                if (ROUND) {
                    v0 = tf32r(v0); v1 = tf32r(v1); v2 = tf32r(v2); v3 = tf32r(v3);
                }
                *(float2*)&out[(size_t)r * N + c]     = make_float2(v0, v1);
                *(float2*)&out[(size_t)(r+8) * N + c] = make_float2(v2, v3);
            }
        }
    }
}

// ---------------------------------------------------------------------------
// Causal attention v2: one (batch, head) per block, 256 threads, 8 warps.
// Warp per query row. Phase 1: lane-per-key scores (no shuffles in the inner
// loop; 65-stride smem => conflict-free). One max/sum shfl reduction per row.
// Phase 2: p transposed via smem; lane-per-dim output accumulation.
// Smem: qs/ks/vs [128][65] + p[8][128]  => 103936 B (occ 1).
// ---------------------------------------------------------------------------
#define ATT_STRIDE 65
#define ATT_SMEM ((3 * NT * ATT_STRIDE + 8 * NT) * 4)

__global__ void __launch_bounds__(256, 1)
attn_kernel(const float* __restrict__ qkv, float* __restrict__ att) {
    extern __shared__ float sm[];
    float* qs = sm;
    float* ks = sm + NT * ATT_STRIDE;
    float* vs = sm + 2 * NT * ATT_STRIDE;
    float* pb = sm + 3 * NT * ATT_STRIDE;    // [8 warps][128]

    int bh = blockIdx.x;
    int b = bh / NH, h = bh % NH;
    size_t rbase = (size_t)(b * NT) * NQKV + h * NHS;
    int tid = threadIdx.x;
    int warp = tid >> 5, lane = tid & 31;

    // Load q/k/v tiles (coalesced: consecutive threads -> consecutive d)
    for (int e = tid; e < NT * NHS; e += 256) {
        int t = e >> 6, d = e & 63;
        size_t src = rbase + (size_t)t * NQKV + d;
        qs[t * ATT_STRIDE + d] = qkv[src];
        ks[t * ATT_STRIDE + d] = qkv[src + NC];
        vs[t * ATT_STRIDE + d] = qkv[src + 2*NC];
    }
    __syncthreads();

    const float scale = 0.0625f;   // C^-0.5 (C=256), per reference
    float* pw = pb + warp * NT;

    for (int tq = warp; tq < NT; tq += 8) {
        // ---- scores: lane owns keys lane, lane+32, lane+64, lane+96 ----
        float a0 = 0.f, a1 = 0.f, a2 = 0.f, a3 = 0.f;
        const float* qrow = qs + tq * ATT_STRIDE;
        const float* k0 = ks + lane * ATT_STRIDE;
        #pragma unroll 8
        for (int d = 0; d < NHS; d++) {
            float qd = qrow[d];                          // broadcast
            a0 += qd * k0[d];
            a1 += qd * k0[32 * ATT_STRIDE + d];
            a2 += qd * k0[64 * ATT_STRIDE + d];
            a3 += qd * k0[96 * ATT_STRIDE + d];
        }
        a0 = (lane      <= tq) ? a0 * scale : -1e30f;
        a1 = (lane + 32 <= tq) ? a1 * scale : -1e30f;
        a2 = (lane + 64 <= tq) ? a2 * scale : -1e30f;
        a3 = (lane + 96 <= tq) ? a3 * scale : -1e30f;

        // ---- softmax: one warp reduction for max, one for sum ----
        float m = fmaxf(fmaxf(a0, a1), fmaxf(a2, a3));
        #pragma unroll
        for (int o = 16; o; o >>= 1) m = fmaxf(m, __shfl_xor_sync(0xffffffffu, m, o));
        float p0 = __expf(a0 - m), p1 = __expf(a1 - m);
        float p2 = __expf(a2 - m), p3 = __expf(a3 - m);
        float l = p0 + p1 + p2 + p3;
        #pragma unroll
        for (int o = 16; o; o >>= 1) l += __shfl_xor_sync(0xffffffffu, l, o);
        float inv = 1.0f / l;

        pw[lane]      = p0;
        pw[lane + 32] = p1;
        pw[lane + 64] = p2;
        pw[lane + 96] = p3;
        __syncwarp();

        // ---- output: lane owns dims lane and lane+32 ----
        float o0 = 0.f, o1 = 0.f;
        const float* v0p = vs + lane;
        int jmax = tq + 1;
        for (int j = 0; j < jmax; j++) {
            float pj = pw[j];                            // broadcast
            o0 += pj * v0p[j * ATT_STRIDE];
            o1 += pj * v0p[j * ATT_STRIDE + 32];
        }
        size_t obase = (size_t)(b * NT + tq) * NC + h * NHS;
        att[obase + lane]      = tf32r(o0 * inv);
        att[obase + lane + 32] = tf32r(o1 * inv);
        __syncwarp();
    }
}

// ---------------------------------------------------------------------------
// Host launcher
// ---------------------------------------------------------------------------
extern "C" void kernel_launch(void* const* d_in, const int* in_sizes, int n_in,
                              void* d_out, int out_size) {
    const int*   idx     = (const int*)  d_in[0];
    const float* tok_emb = (const float*)d_in[1];
    const float* pos_emb = (const float*)d_in[2];
    const float* ln1_g   = (const float*)d_in[3];
    const float* ln1_b   = (const float*)d_in[4];
    const float* wq      = (const float*)d_in[5];
    const float* wk      = (const float*)d_in[6];
    const float* wv      = (const float*)d_in[7];
    const float* proj_w  = (const float*)d_in[8];
    const float* proj_b  = (const float*)d_in[9];
    const float* ln2_g   = (const float*)d_in[10];
    const float* ln2_b   = (const float*)d_in[11];
    const float* w1      = (const float*)d_in[12];
    const float* b1      = (const float*)d_in[13];
    const float* w2      = (const float*)d_in[14];
    const float* b2      = (const float*)d_in[15];
    const float* lnf_g   = (const float*)d_in[16];
    const float* lnf_b   = (const float*)d_in[17];
    const float* lm_w    = (const float*)d_in[18];
    const float* lm_b    = (const float*)d_in[19];
    float* out = (float*)d_out;

    float *x, *h, *qkv, *att, *ff;
    float *wqkv, *projw, *pw1, *pw2, *lmw;
    cudaGetSymbolAddress((void**)&x,    g_x);
    cudaGetSymbolAddress((void**)&h,    g_h);
    cudaGetSymbolAddress((void**)&qkv,  g_qkv);
    cudaGetSymbolAddress((void**)&att,  g_att);
    cudaGetSymbolAddress((void**)&ff,   g_ff);
    cudaGetSymbolAddress((void**)&wqkv, g_wqkv);
    cudaGetSymbolAddress((void**)&projw,g_projw);
    cudaGetSymbolAddress((void**)&pw1,  g_w1);
    cudaGetSymbolAddress((void**)&pw2,  g_w2);
    cudaGetSymbolAddress((void**)&lmw,  g_lmw);

    cudaFuncSetAttribute(attn_kernel, cudaFuncAttributeMaxDynamicSharedMemorySize, ATT_SMEM);
    cudaFuncSetAttribute(mma_gemm<false,false,false,false>,
                         cudaFuncAttributeMaxDynamicSharedMemorySize, GEMM_SMEM);
    cudaFuncSetAttribute(mma_gemm<true,true,false,false>,
                         cudaFuncAttributeMaxDynamicSharedMemorySize, GEMM_SMEM);
    cudaFuncSetAttribute(mma_gemm<true,false,true,true>,
                         cudaFuncAttributeMaxDynamicSharedMemorySize, GEMM_SMEM);
    cudaFuncSetAttribute(mma_gemm<true,false,false,false>,
                         cudaFuncAttributeMaxDynamicSharedMemorySize, GEMM_SMEM);

    // ---- weight pre-round / pack ----
    pack_qkv_kernel<<<(NL*NC*NC)/256, 256>>>(wq, wk, wv);
    round_kernel<<<(NL*NC*NC/4 + 255)/256, 256>>>(proj_w, projw, NL*NC*NC/4);
    round_kernel<<<(NL*NC*NDFF/4 + 255)/256, 256>>>(w1, pw1, NL*NC*NDFF/4);
    round_kernel<<<(NL*NDFF*NC/4 + 255)/256, 256>>>(w2, pw2, NL*NDFF*NC/4);
    round_kernel<<<(NC*NV/4 + 255)/256, 256>>>(lm_w, lmw, NC*NV/4);

    embed_kernel<<<NBT, NC>>>(idx, tok_emb, pos_emb);

    for (int l = 0; l < NL; l++) {
        ln_kernel<<<NBT / 8, 256>>>(x, h, ln1_g + l*NC, ln1_b + l*NC);
        mma_gemm<false,false,false,false><<<dim3(NQKV/128, NBT/128), 256, GEMM_SMEM>>>(
            h, wqkv + (size_t)l*NC*NQKV, nullptr, nullptr, qkv, NBT, NQKV, NC);
        attn_kernel<<<NB * NH, 256, ATT_SMEM>>>(qkv, att);
        mma_gemm<true,true,false,false><<<dim3(NC/128, NBT/128), 256, GEMM_SMEM>>>(
            att, projw + (size_t)l*NC*NC, proj_b + l*NC, x, x, NBT, NC, NC);
        ln_kernel<<<NBT / 8, 256>>>(x, h, ln2_g + l*NC, ln2_b + l*NC);
        mma_gemm<true,false,true,true><<<dim3(NDFF/128, NBT/128), 256, GEMM_SMEM>>>(
            h, pw1 + (size_t)l*NC*NDFF, b1 + l*NDFF, nullptr, ff, NBT, NDFF, NC);
        mma_gemm<true,true,false,false><<<dim3(NC/128, NBT/128), 256, GEMM_SMEM>>>(
            ff, pw2 + (size_t)l*NDFF*NC, b2 + l*NC, x, x, NBT, NC, NDFF);
    }

    ln_kernel<<<NBT / 8, 256>>>(x, h, lnf_g, lnf_b);
    mma_gemm<true,false,false,false><<<dim3((NV + 127)/128, NBT/128), 256, GEMM_SMEM>>>(
        h, lmw, lm_b, nullptr, out, NBT, NV, NC);
}